// round 15
// baseline (speedup 1.0000x reference)
#include <cuda_runtime.h>
#include <math_constants.h>

// ---------------------------------------------------------------------------
// NeuralSpectralBlock2D  (B=16, C=64, H=W=240, P=3, HEAD=8, dh=8, T=4, M=12)
// tf32 tensor-core GEMM per CTA:  Y[160 x 72] = W[160 x 64] * X[64 x 72]
// R15 = R12/R14 skeleton + pair-scoped NAMED BARRIERS in the epilogue:
// each patch is owned by warps {patch, patch+8}; P1/P2/P3 sync via
// bar.sync(patch+1, 64) instead of CTA-wide __syncthreads -> phases of
// different patches overlap (MUFU/LDS pipe mixing, less barrier skew).
// ---------------------------------------------------------------------------

#define Bn    16
#define Cn    64
#define Hn    240
#define Wn    240
#define NP    8
#define NT    512

#define HPn   80
#define WPn   80
#define WBLK  (WPn / NP)          // 10
#define GRID  (Bn * HPn * WBLK)   // 12800

#define SW  168           // W^T stride: bank = 8t+g -> conflict-free
#define SXK 72            // X stride (k-major): 72 mod 32 = 8 -> conflict-free
#define SY  73            // Y stride

#define W_F   (64 * SW)           // 10752
#define Y_F   (160 * SY)          // 11680
#define X_F   (64 * SXK)          // 4608

#define SPB   768                 // per-patch at/lp region (64*12)
#define XR_F  (NP * SPB)          // 6144 >= X_F

// small consts
#define S_B   0                   // biasAll[160]
#define S_WT  160                 // wt[m'][c] 1536
#define S_Q   1696                // q[hd][t]  256
#define S_SZ  1952

#define OFF_X   Y_F               // X during GEMM; at/lp (8x768) after
#define OFF_SS  (OFF_X + XR_F)
#define SMEM_F  (OFF_SS + S_SZ)       // 19776 floats
#define SMEM_B  (SMEM_F * 4)          // 79104 bytes -> 2 CTAs/SM

#define PAIR_BAR(id) asm volatile("bar.sync %0, 64;" :: "r"(id) : "memory")

__device__ __align__(16) float g_W[W_F];
__device__ __align__(16) float g_small[S_SZ];

__device__ __forceinline__ float to_tf32(float v) {
    unsigned o;
    asm("cvt.rna.tf32.f32 %0, %1;" : "=r"(o) : "f"(v));
    return __uint_as_float(o);
}

__device__ __forceinline__ void mma_tf32(float c[4],
                                         unsigned a0, unsigned a1,
                                         unsigned a2, unsigned a3,
                                         unsigned b0, unsigned b1) {
    asm volatile(
        "mma.sync.aligned.m16n8k8.row.col.f32.tf32.tf32.f32 "
        "{%0,%1,%2,%3}, {%4,%5,%6,%7}, {%8,%9}, {%0,%1,%2,%3};\n"
        : "+f"(c[0]), "+f"(c[1]), "+f"(c[2]), "+f"(c[3])
        : "r"(a0), "r"(a1), "r"(a2), "r"(a3), "r"(b0), "r"(b1));
}

// ---------------- setup: fold constants, build W^T (tf32) ----------------
__global__ void setup_kernel(const float* __restrict__ latent,
                             const float* __restrict__ weights,
                             const float* __restrict__ enc_w,
                             const float* __restrict__ enc_b,
                             const float* __restrict__ dec_w,
                             const float* __restrict__ dec_b) {
    int tid = threadIdx.x;
    for (int i = tid; i < 160 * 64; i += 256) {
        int m = i >> 6, k = i & 63;
        float val;
        if (m < 32) {                       // folded scores1: A[c][ht]
            int h = m >> 2, t = m & 3;
            val = 0.f;
            for (int d = 0; d < 8; d++)
                val += latent[h * 32 + t * 8 + d]
                     * enc_w[(h * 16 + 2 * d) * 64 + k];
        } else if (m < 96) {                // v weights
            int hd = m - 32, h = hd >> 3, d = hd & 7;
            val = enc_w[(h * 16 + 2 * d + 1) * 64 + k];
        } else {                            // dec weights
            val = dec_w[(m - 96) * 64 + k];
        }
        g_W[k * SW + m] = to_tf32(val);
    }
    for (int i = tid; i < 160; i += 256) {
        float val;
        if (i < 32) {
            int h = i >> 2, t = i & 3;
            val = 0.f;
            for (int d = 0; d < 8; d++)
                val += latent[h * 32 + t * 8 + d] * enc_b[h * 16 + 2 * d];
        } else if (i < 96) {
            int hd = i - 32, h = hd >> 3, d = hd & 7;
            val = enc_b[h * 16 + 2 * d + 1];
        } else {
            val = dec_b[i - 96];
        }
        g_small[S_B + i] = val;
    }
    for (int i = tid; i < 1536; i += 256) {
        int m = i >> 6, c = i & 63;
        g_small[S_WT + i] = weights[c * 24 + m];
    }
    for (int i = tid; i < 256; i += 256) {
        int hd = i >> 2, t = i & 3;
        int h = hd >> 3, d = hd & 7;
        g_small[S_Q + i] = latent[h * 32 + t * 8 + d];
    }
}

// ---------------- main fused kernel ----------------
__global__ void __launch_bounds__(NT, 2)
nsb_kernel(const float* __restrict__ x, float* __restrict__ out) {
    extern __shared__ float sm[];
    float* wy  = sm;                 // W^T during GEMM, Y afterwards
    float* xs  = sm + OFF_X;         // X (k-major) during GEMM; at/lp after
    float* ss  = sm + OFF_SS;
    float* spb = xs;                 // per-patch at/lp (overlay, SPB/patch)

    const int tid = threadIdx.x;

    // W^T -> smem
    {
        const float4* src = (const float4*)g_W;
        float4* dst = (float4*)wy;
        for (int i = tid; i < W_F / 4; i += NT) dst[i] = src[i];
    }
    for (int i = tid; i < S_SZ; i += NT) ss[i] = g_small[i];

    const int cta  = blockIdx.x;
    const int wblk = cta % WBLK;
    const int hp   = (cta / WBLK) % HPn;
    const int b    = cta / (WBLK * HPn);

    // patchify: float4 loads; X[k][n] k-major (raw fp32; HW truncates to tf32)
    for (int i = tid; i < 1152; i += NT) {
        int c  = i / 18;
        int r  = i - c * 18;
        int p0 = r / 6;
        int q  = r - p0 * 6;
        float4 v = *(const float4*)(x + ((size_t)(b * 64 + c) * Hn
                                         + hp * 3 + p0) * Wn + wblk * 24 + 4 * q);
#pragma unroll
        for (int j = 0; j < 4; j++) {
            int col = 4 * q + j;
            int wl = col / 3, p1 = col - wl * 3;
            xs[c * SXK + wl * 9 + p0 * 3 + p1] = ((const float*)&v)[j];
        }
    }
    __syncthreads();

    const int warp = tid >> 5;
    const int lane = tid & 31;
    const int g = lane >> 2, t = lane & 3;

    // ================= GEMM: 15-warp grid 5m x 3n =================
    float acc[2][3][4];
    const int wm = warp / 3, wn = warp - wm * 3;
    const int m0 = wm * 32, n0 = wn * 24;
    if (warp < 15) {
#pragma unroll
        for (int mt = 0; mt < 2; mt++)
#pragma unroll
            for (int nt = 0; nt < 3; nt++)
#pragma unroll
                for (int j = 0; j < 4; j++) acc[mt][nt][j] = 0.f;
#pragma unroll 2
        for (int k0 = 0; k0 < 64; k0 += 8) {
            unsigned bf[3][2];
#pragma unroll
            for (int nt = 0; nt < 3; nt++) {
                bf[nt][0] = __float_as_uint(xs[(k0 + t) * SXK + n0 + nt * 8 + g]);
                bf[nt][1] = __float_as_uint(xs[(k0 + t + 4) * SXK + n0 + nt * 8 + g]);
            }
#pragma unroll
            for (int mt = 0; mt < 2; mt++) {
                int mr = m0 + mt * 16;
                unsigned a0 = __float_as_uint(wy[(k0 + t) * SW + mr + g]);
                unsigned a1 = __float_as_uint(wy[(k0 + t) * SW + mr + g + 8]);
                unsigned a2 = __float_as_uint(wy[(k0 + t + 4) * SW + mr + g]);
                unsigned a3 = __float_as_uint(wy[(k0 + t + 4) * SW + mr + g + 8]);
#pragma unroll
                for (int nt = 0; nt < 3; nt++)
                    mma_tf32(acc[mt][nt], a0, a1, a2, a3, bf[nt][0], bf[nt][1]);
            }
        }
    }
    __syncthreads();   // all GEMM reads of W/X done -> wy becomes Y, xs free

    if (warp < 15) {
#pragma unroll
        for (int mt = 0; mt < 2; mt++) {
            int r0 = m0 + mt * 16 + g;
            int r1 = r0 + 8;
            float b0 = ss[S_B + r0], b1 = ss[S_B + r1];
#pragma unroll
            for (int nt = 0; nt < 3; nt++) {
                int cc = n0 + nt * 8 + 2 * t;
                wy[r0 * SY + cc]     = acc[mt][nt][0] + b0;
                wy[r0 * SY + cc + 1] = acc[mt][nt][1] + b0;
                wy[r1 * SY + cc]     = acc[mt][nt][2] + b1;
                wy[r1 * SY + cc + 1] = acc[mt][nt][3] + b1;
            }
        }
    }
    __syncthreads();   // Y complete

    // ===== epilogue: each patch owned by warp pair {patch, patch+8} =====
    const int patch = warp & 7;
    const int half  = warp >> 3;
    const int ch    = lane + (half << 5);
    const int bid   = patch + 1;          // named barrier id (0 = default)
    float* at = spb + patch * SPB;        // attn rows stride 12
    float* lp = at;                       // lp[ch*12 + tt] overlays at

    // P1: softmax (half-0 warp; lane = ht)
    if (half == 0) {
        float s1[9];
#pragma unroll
        for (int p = 0; p < 9; p++) s1[p] = wy[lane * SY + patch * 9 + p];
        float mx = s1[0];
#pragma unroll
        for (int p = 1; p < 9; p++) mx = fmaxf(mx, s1[p]);
        float sum = 0.f;
#pragma unroll
        for (int p = 0; p < 9; p++) { s1[p] = __expf(s1[p] - mx); sum += s1[p]; }
        float inv = 1.0f / sum;
        float4 w0 = make_float4(s1[0] * inv, s1[1] * inv, s1[2] * inv, s1[3] * inv);
        float4 w1 = make_float4(s1[4] * inv, s1[5] * inv, s1[6] * inv, s1[7] * inv);
        *(float4*)(at + lane * 12)     = w0;
        *(float4*)(at + lane * 12 + 4) = w1;
        at[lane * 12 + 8] = s1[8] * inv;
    }
    PAIR_BAR(bid);     // attn visible to both warps of the pair

    // P2a: lt = attn1 @ v + q
    float lt[4];
    {
        float v[9];
#pragma unroll
        for (int p = 0; p < 9; p++)
            v[p] = wy[(32 + ch) * SY + patch * 9 + p];
        const int hh = ch >> 3;
#pragma unroll
        for (int tt = 0; tt < 4; tt++) {
            const float* r = at + (hh * 4 + tt) * 12;
            float4 r0 = *(const float4*)(r);
            float4 r1 = *(const float4*)(r + 4);
            float r8 = r[8];
            float a = ss[S_Q + ch * 4 + tt];
            a = fmaf(r0.x, v[0], a); a = fmaf(r0.y, v[1], a);
            a = fmaf(r0.z, v[2], a); a = fmaf(r0.w, v[3], a);
            a = fmaf(r1.x, v[4], a); a = fmaf(r1.y, v[5], a);
            a = fmaf(r1.z, v[6], a); a = fmaf(r1.w, v[7], a);
            a = fmaf(r8,   v[8], a);
            lt[tt] = a;
        }
    }
    PAIR_BAR(bid);     // both warps done reading attn before lp overwrite

    // P2b: spectral (Chebyshev recurrence, m-outer) -> lp
    {
        float c2[4], scur[4], ccur[4], sprev[4], cprev[4], acc0[4];
        float w0c = ss[S_WT + 12 * 64 + ch];           // m=0: sin=0, cos=1
#pragma unroll
        for (int tt = 0; tt < 4; tt++) {
            float base = lt[tt] * (float)(CUDART_PI / 12.0);
            float s0, c0;
            __sincosf(base, &s0, &c0);
            c2[tt] = 2.0f * c0;
            scur[tt] = s0; ccur[tt] = c0;
            sprev[tt] = 0.f; cprev[tt] = 1.f;
            acc0[tt] = w0c;
        }
#pragma unroll
        for (int m = 1; m < 12; m++) {
            float ws = ss[S_WT + m * 64 + ch];
            float wc = ss[S_WT + (12 + m) * 64 + ch];
#pragma unroll
            for (int tt = 0; tt < 4; tt++) {
                acc0[tt] = fmaf(scur[tt], ws, fmaf(ccur[tt], wc, acc0[tt]));
                float sn = fmaf(c2[tt], scur[tt], -sprev[tt]);
                float cn = fmaf(c2[tt], ccur[tt], -cprev[tt]);
                sprev[tt] = scur[tt]; cprev[tt] = ccur[tt];
                scur[tt] = sn; ccur[tt] = cn;
            }
        }
        float4 o = make_float4(lt[0] + acc0[0], lt[1] + acc0[1],
                               lt[2] + acc0[2], lt[3] + acc0[3]);
        *(float4*)(lp + ch * 12) = o;
    }
    PAIR_BAR(bid);     // lp complete for this patch

    // P3: decoder attention (72 items = h x pos), split by pair half
    {
        float* xq = wy + 96 * SY + patch * 9;
#pragma unroll
        for (int k = 0; k < 2; k++) {
            int item = half * 36 + k * 32 + lane;
            if (k == 0 || lane < 4) {
                int h = item / 9, pos = item - h * 9;
                float sc[4] = {0.f, 0.f, 0.f, 0.f};
#pragma unroll
                for (int d = 0; d < 8; d++) {
                    float xv = xq[(h * 8 + d) * SY + pos];
                    float4 l = *(const float4*)(lp + (h * 8 + d) * 12);
                    sc[0] = fmaf(xv, l.x, sc[0]);
                    sc[1] = fmaf(xv, l.y, sc[1]);
                    sc[2] = fmaf(xv, l.z, sc[2]);
                    sc[3] = fmaf(xv, l.w, sc[3]);
                }
                float m2 = fmaxf(fmaxf(sc[0], sc[1]), fmaxf(sc[2], sc[3]));
                float es = 0.f;
#pragma unroll
                for (int tt = 0; tt < 4; tt++) {
                    sc[tt] = __expf(sc[tt] - m2); es += sc[tt];
                }
                float inv = 1.0f / es;
#pragma unroll
                for (int tt = 0; tt < 4; tt++) sc[tt] *= inv;
#pragma unroll
                for (int d = 0; d < 8; d++) {
                    float4 l = *(const float4*)(lp + (h * 8 + d) * 12);
                    float o = sc[0] * l.x;
                    o = fmaf(sc[1], l.y, o);
                    o = fmaf(sc[2], l.z, o);
                    o = fmaf(sc[3], l.w, o);
                    xq[(h * 8 + d) * SY + pos] = o;
                }
            }
        }
    }
    __syncthreads();   // all patches' xo complete (unpatchify crosses patches)

    // un-patchify: float4 residual read + float4 store
    for (int i = tid; i < 1152; i += NT) {
        int c  = i / 18;
        int r  = i - c * 18;
        int p0 = r / 6;
        int q  = r - p0 * 6;
        size_t gbase = ((size_t)(b * 64 + c) * Hn + hp * 3 + p0) * Wn
                       + wblk * 24 + 4 * q;
        float4 rx = *(const float4*)(x + gbase);
        float4 o;
#pragma unroll
        for (int j = 0; j < 4; j++) {
            int col = 4 * q + j;
            int wl = col / 3, p1 = col - wl * 3;
            ((float*)&o)[j] = wy[(96 + c) * SY + wl * 9 + p0 * 3 + p1]
                              + ((const float*)&rx)[j];
        }
        *(float4*)(out + gbase) = o;
    }
}

extern "C" void kernel_launch(void* const* d_in, const int* in_sizes, int n_in,
                              void* d_out, int out_size) {
    const float* x       = (const float*)d_in[0];
    const float* latent  = (const float*)d_in[1];
    const float* weights = (const float*)d_in[2];
    const float* enc_w   = (const float*)d_in[3];
    const float* enc_b   = (const float*)d_in[4];
    const float* dec_w   = (const float*)d_in[5];
    const float* dec_b   = (const float*)d_in[6];
    float* out = (float*)d_out;

    cudaFuncSetAttribute(nsb_kernel,
                         cudaFuncAttributeMaxDynamicSharedMemorySize, SMEM_B);

    setup_kernel<<<1, 256>>>(latent, weights, enc_w, enc_b, dec_w, dec_b);
    nsb_kernel<<<GRID, NT, SMEM_B>>>(x, out);
}

// round 16
// speedup vs baseline: 1.0250x; 1.0250x over previous
#include <cuda_runtime.h>
#include <math_constants.h>

// ---------------------------------------------------------------------------
// NeuralSpectralBlock2D  (B=16, C=64, H=W=240, P=3, HEAD=8, dh=8, T=4, M=12)
// tf32 tensor-core GEMM per CTA:  Y[160 x 72] = W[160 x 64] * X[64 x 72]
// R16 = R12 (best) with k-interleaved PAIRED fragment layouts:
//   Wp2[kk][m] = {W[k][m], W[k+4][m]}  stride 164 float2 (== 4 mod 16)
//   X2 [kk][n] = {X[k][n], X[k+4][n]}  stride  84 float2 (== 4 mod 16)
// -> A frags 2x LDS.64, B frags 1x LDS.64, conflict-free per half-warp phase.
// Everything else (epilogue, patchify/unpatchify, strides) identical to R12.
// ---------------------------------------------------------------------------

#define Bn    16
#define Cn    64
#define Hn    240
#define Wn    240
#define NP    8
#define NT    512

#define HPn   80
#define WPn   80
#define WBLK  (WPn / NP)          // 10
#define GRID  (Bn * HPn * WBLK)   // 12800

#define SWK2 164          // W pair stride in float2 units (164 mod 16 = 4)
#define SX2  84           // X pair stride in float2 units ( 84 mod 16 = 4)
#define SY   73           // Y stride (floats)

#define W_F   (32 * SWK2 * 2)     // 10496 floats
#define Y_F   (160 * SY)          // 11680 floats
#define WY_F  11680               // max(W_F, Y_F)
#define X_F   (32 * SX2 * 2)      // 5376 floats

// small consts
#define S_B   0                   // biasAll[160]
#define S_WT  160                 // wt[m'][c] 1536
#define S_Q   1696                // q[hd][t]  256
#define S_SZ  1952

#define OFF_X   WY_F              // X2 during GEMM; at/lp (8x320) after
#define OFF_SS  (OFF_X + X_F)
#define SMEM_F  (OFF_SS + S_SZ)       // 19008 floats
#define SMEM_B  (SMEM_F * 4)          // 76032 bytes -> 2 CTAs/SM

__device__ __align__(16) float g_W[W_F];
__device__ __align__(16) float g_small[S_SZ];

__device__ __forceinline__ float to_tf32(float v) {
    unsigned o;
    asm("cvt.rna.tf32.f32 %0, %1;" : "=r"(o) : "f"(v));
    return __uint_as_float(o);
}

__device__ __forceinline__ void mma_tf32(float c[4],
                                         unsigned a0, unsigned a1,
                                         unsigned a2, unsigned a3,
                                         unsigned b0, unsigned b1) {
    asm volatile(
        "mma.sync.aligned.m16n8k8.row.col.f32.tf32.tf32.f32 "
        "{%0,%1,%2,%3}, {%4,%5,%6,%7}, {%8,%9}, {%0,%1,%2,%3};\n"
        : "+f"(c[0]), "+f"(c[1]), "+f"(c[2]), "+f"(c[3])
        : "r"(a0), "r"(a1), "r"(a2), "r"(a3), "r"(b0), "r"(b1));
}

// ---------------- setup: fold constants, build paired W (tf32) -------------
__global__ void setup_kernel(const float* __restrict__ latent,
                             const float* __restrict__ weights,
                             const float* __restrict__ enc_w,
                             const float* __restrict__ enc_b,
                             const float* __restrict__ dec_w,
                             const float* __restrict__ dec_b) {
    int tid = threadIdx.x;
    for (int i = tid; i < 160 * 64; i += 256) {
        int m = i >> 6, k = i & 63;
        float val;
        if (m < 32) {                       // folded scores1: A[c][ht]
            int h = m >> 2, t = m & 3;
            val = 0.f;
            for (int d = 0; d < 8; d++)
                val += latent[h * 32 + t * 8 + d]
                     * enc_w[(h * 16 + 2 * d) * 64 + k];
        } else if (m < 96) {                // v weights
            int hd = m - 32, h = hd >> 3, d = hd & 7;
            val = enc_w[(h * 16 + 2 * d + 1) * 64 + k];
        } else {                            // dec weights
            val = dec_w[(m - 96) * 64 + k];
        }
        // k-interleaved pair layout: kk row holds {W[k], W[k+4]} per m
        int kk = (k >> 3) * 4 + (k & 3);
        int hi = (k >> 2) & 1;
        g_W[(kk * SWK2 + m) * 2 + hi] = to_tf32(val);
    }
    for (int i = tid; i < 160; i += 256) {
        float val;
        if (i < 32) {
            int h = i >> 2, t = i & 3;
            val = 0.f;
            for (int d = 0; d < 8; d++)
                val += latent[h * 32 + t * 8 + d] * enc_b[h * 16 + 2 * d];
        } else if (i < 96) {
            int hd = i - 32, h = hd >> 3, d = hd & 7;
            val = enc_b[h * 16 + 2 * d + 1];
        } else {
            val = dec_b[i - 96];
        }
        g_small[S_B + i] = val;
    }
    for (int i = tid; i < 1536; i += 256) {
        int m = i >> 6, c = i & 63;
        g_small[S_WT + i] = weights[c * 24 + m];
    }
    for (int i = tid; i < 256; i += 256) {
        int hd = i >> 2, t = i & 3;
        int h = hd >> 3, d = hd & 7;
        g_small[S_Q + i] = latent[h * 32 + t * 8 + d];
    }
}

// ---------------- main fused kernel ----------------
__global__ void __launch_bounds__(NT, 2)
nsb_kernel(const float* __restrict__ x, float* __restrict__ out) {
    extern __shared__ float sm[];
    float* wy  = sm;                 // paired W during GEMM, Y afterwards
    float* xs  = sm + OFF_X;         // paired X during GEMM; at/lp after
    float* ss  = sm + OFF_SS;
    float* spb = xs;                 // per-patch at/lp (overlay, 320/patch)

    const int tid = threadIdx.x;

    // W -> smem
    {
        const float4* src = (const float4*)g_W;
        float4* dst = (float4*)wy;
        for (int i = tid; i < W_F / 4; i += NT) dst[i] = src[i];
    }
    for (int i = tid; i < S_SZ; i += NT) ss[i] = g_small[i];

    const int cta  = blockIdx.x;
    const int wblk = cta % WBLK;
    const int hp   = (cta / WBLK) % HPn;
    const int b    = cta / (WBLK * HPn);

    // patchify: float4 loads; X2 pair layout {k, k+4} (raw fp32 -> HW tf32)
    for (int i = tid; i < 1152; i += NT) {
        int c  = i / 18;
        int r  = i - c * 18;
        int p0 = r / 6;
        int q  = r - p0 * 6;
        float4 v = *(const float4*)(x + ((size_t)(b * 64 + c) * Hn
                                         + hp * 3 + p0) * Wn + wblk * 24 + 4 * q);
        int kk = (c >> 3) * 4 + (c & 3);
        int hi = (c >> 2) & 1;
#pragma unroll
        for (int j = 0; j < 4; j++) {
            int col = 4 * q + j;
            int wl = col / 3, p1 = col - wl * 3;
            int n = wl * 9 + p0 * 3 + p1;
            xs[(kk * SX2 + n) * 2 + hi] = ((const float*)&v)[j];
        }
    }
    __syncthreads();

    const int warp = tid >> 5;
    const int lane = tid & 31;
    const int g = lane >> 2, t = lane & 3;

    // ================= GEMM: 15-warp grid 5m x 3n =================
    float acc[2][3][4];
    const int wm = warp / 3, wn = warp - wm * 3;
    const int m0 = wm * 32, n0 = wn * 24;
    if (warp < 15) {
#pragma unroll
        for (int mt = 0; mt < 2; mt++)
#pragma unroll
            for (int nt = 0; nt < 3; nt++)
#pragma unroll
                for (int j = 0; j < 4; j++) acc[mt][nt][j] = 0.f;
        const float2* w2 = (const float2*)wy;
        const float2* x2 = (const float2*)xs;
#pragma unroll 2
        for (int k0 = 0; k0 < 64; k0 += 8) {
            int kk = (k0 >> 3) * 4 + t;
            float2 bf[3];
#pragma unroll
            for (int nt = 0; nt < 3; nt++)
                bf[nt] = x2[kk * SX2 + n0 + nt * 8 + g];   // {b0, b1}
#pragma unroll
            for (int mt = 0; mt < 2; mt++) {
                int mr = m0 + mt * 16;
                float2 alo = w2[kk * SWK2 + mr + g];       // {a0, a2}
                float2 ahi = w2[kk * SWK2 + mr + g + 8];   // {a1, a3}
#pragma unroll
                for (int nt = 0; nt < 3; nt++)
                    mma_tf32(acc[mt][nt],
                             __float_as_uint(alo.x), __float_as_uint(ahi.x),
                             __float_as_uint(alo.y), __float_as_uint(ahi.y),
                             __float_as_uint(bf[nt].x), __float_as_uint(bf[nt].y));
            }
        }
    }
    __syncthreads();   // all GEMM reads of W/X done -> wy becomes Y, xs free

    if (warp < 15) {
#pragma unroll
        for (int mt = 0; mt < 2; mt++) {
            int r0 = m0 + mt * 16 + g;
            int r1 = r0 + 8;
            float b0 = ss[S_B + r0], b1 = ss[S_B + r1];
#pragma unroll
            for (int nt = 0; nt < 3; nt++) {
                int cc = n0 + nt * 8 + 2 * t;
                wy[r0 * SY + cc]     = acc[mt][nt][0] + b0;
                wy[r0 * SY + cc + 1] = acc[mt][nt][1] + b0;
                wy[r1 * SY + cc]     = acc[mt][nt][2] + b1;
                wy[r1 * SY + cc + 1] = acc[mt][nt][3] + b1;
            }
        }
    }
    __syncthreads();   // Y complete

    // ===== P1: softmax (warps 0-7, warp = patch; lane = ht) =====
    if (warp < 8) {
        float* at = spb + warp * 320;
        float s1[9];
#pragma unroll
        for (int p = 0; p < 9; p++) s1[p] = wy[lane * SY + warp * 9 + p];
        float mx = s1[0];
#pragma unroll
        for (int p = 1; p < 9; p++) mx = fmaxf(mx, s1[p]);
        float sum = 0.f;
#pragma unroll
        for (int p = 0; p < 9; p++) { s1[p] = __expf(s1[p] - mx); sum += s1[p]; }
        float inv = 1.0f / sum;
#pragma unroll
        for (int p = 0; p < 9; p++) at[lane * 9 + p] = s1[p] * inv;
    }
    __syncthreads();

    // ===== P2: lt + spectral, 2 warps/patch (channel halves) =====
    const int patch = warp & 7;
    const int half  = warp >> 3;
    const int ch    = lane + (half << 5);
    float* at = spb + patch * 320;
    float* lp = at;

    float lt[4];
    {
        float v[9];
#pragma unroll
        for (int p = 0; p < 9; p++)
            v[p] = wy[(32 + ch) * SY + patch * 9 + p];
        const int hh = ch >> 3;
#pragma unroll
        for (int tt = 0; tt < 4; tt++) {
            float a = ss[S_Q + ch * 4 + tt];
            const float* r = at + (hh * 4 + tt) * 9;
#pragma unroll
            for (int p = 0; p < 9; p++) a = fmaf(r[p], v[p], a);
            lt[tt] = a;
        }
    }
    __syncthreads();   // all reads of attn1 done before lp overwrite

    // spectral: Chebyshev recurrence, m-outer (2 LDS per m)
    {
        float c2[4], scur[4], ccur[4], sprev[4], cprev[4], acc0[4];
        float w0c = ss[S_WT + 12 * 64 + ch];           // m=0: sin=0, cos=1
#pragma unroll
        for (int tt = 0; tt < 4; tt++) {
            float base = lt[tt] * (float)(CUDART_PI / 12.0);
            float s0, c0;
            __sincosf(base, &s0, &c0);
            c2[tt] = 2.0f * c0;
            scur[tt] = s0; ccur[tt] = c0;
            sprev[tt] = 0.f; cprev[tt] = 1.f;
            acc0[tt] = w0c;
        }
#pragma unroll
        for (int m = 1; m < 12; m++) {
            float ws = ss[S_WT + m * 64 + ch];
            float wc = ss[S_WT + (12 + m) * 64 + ch];
#pragma unroll
            for (int tt = 0; tt < 4; tt++) {
                acc0[tt] = fmaf(scur[tt], ws, fmaf(ccur[tt], wc, acc0[tt]));
                float sn = fmaf(c2[tt], scur[tt], -sprev[tt]);
                float cn = fmaf(c2[tt], ccur[tt], -cprev[tt]);
                sprev[tt] = scur[tt]; cprev[tt] = ccur[tt];
                scur[tt] = sn; ccur[tt] = cn;
            }
        }
#pragma unroll
        for (int tt = 0; tt < 4; tt++)
            lp[ch * 5 + tt] = lt[tt] + acc0[tt];
    }
    __syncthreads();   // lp complete

    // ===== P3: decoder attention, 2 warps/patch (item halves) =====
    {
        float* xq = wy + 96 * SY + patch * 9;
#pragma unroll
        for (int k = 0; k < 2; k++) {
            int item = half * 36 + k * 32 + lane;
            if (k == 0 || lane < 4) {
                int h = item / 9, pos = item - h * 9;
                float sc[4] = {0.f, 0.f, 0.f, 0.f};
#pragma unroll
                for (int d = 0; d < 8; d++) {
                    float xv = xq[(h * 8 + d) * SY + pos];
                    const float* lr = lp + (h * 8 + d) * 5;
#pragma unroll
                    for (int tt = 0; tt < 4; tt++)
                        sc[tt] = fmaf(xv, lr[tt], sc[tt]);
                }
                float m2 = fmaxf(fmaxf(sc[0], sc[1]), fmaxf(sc[2], sc[3]));
                float es = 0.f;
#pragma unroll
                for (int tt = 0; tt < 4; tt++) {
                    sc[tt] = __expf(sc[tt] - m2); es += sc[tt];
                }
                float inv = 1.0f / es;
#pragma unroll
                for (int tt = 0; tt < 4; tt++) sc[tt] *= inv;
#pragma unroll
                for (int d = 0; d < 8; d++) {
                    const float* lr = lp + (h * 8 + d) * 5;
                    float o = 0.f;
#pragma unroll
                    for (int tt = 0; tt < 4; tt++)
                        o = fmaf(sc[tt], lr[tt], o);
                    xq[(h * 8 + d) * SY + pos] = o;
                }
            }
        }
    }
    __syncthreads();

    // un-patchify: float4 residual read + float4 store
    for (int i = tid; i < 1152; i += NT) {
        int c  = i / 18;
        int r  = i - c * 18;
        int p0 = r / 6;
        int q  = r - p0 * 6;
        size_t gbase = ((size_t)(b * 64 + c) * Hn + hp * 3 + p0) * Wn
                       + wblk * 24 + 4 * q;
        float4 rx = *(const float4*)(x + gbase);
        float4 o;
#pragma unroll
        for (int j = 0; j < 4; j++) {
            int col = 4 * q + j;
            int wl = col / 3, p1 = col - wl * 3;
            ((float*)&o)[j] = wy[(96 + c) * SY + wl * 9 + p0 * 3 + p1]
                              + ((const float*)&rx)[j];
        }
        *(float4*)(out + gbase) = o;
    }
}

extern "C" void kernel_launch(void* const* d_in, const int* in_sizes, int n_in,
                              void* d_out, int out_size) {
    const float* x       = (const float*)d_in[0];
    const float* latent  = (const float*)d_in[1];
    const float* weights = (const float*)d_in[2];
    const float* enc_w   = (const float*)d_in[3];
    const float* enc_b   = (const float*)d_in[4];
    const float* dec_w   = (const float*)d_in[5];
    const float* dec_b   = (const float*)d_in[6];
    float* out = (float*)d_out;

    cudaFuncSetAttribute(nsb_kernel,
                         cudaFuncAttributeMaxDynamicSharedMemorySize, SMEM_B);

    setup_kernel<<<1, 256>>>(latent, weights, enc_w, enc_b, dec_w, dec_b);
    nsb_kernel<<<GRID, NT, SMEM_B>>>(x, out);
}

// round 17
// speedup vs baseline: 1.0325x; 1.0073x over previous
#include <cuda_runtime.h>
#include <math_constants.h>

// ---------------------------------------------------------------------------
// NeuralSpectralBlock2D  (B=16, C=64, H=W=240, P=3, HEAD=8, dh=8, T=4, M=12)
// tf32 tensor-core GEMM per CTA:  Y[160 x 72] = W[160 x 64] * X[64 x 72]
// R17 = R16 (k-paired conflict-free frags) + explicit register DOUBLE
// BUFFERING in the k-loop: next k-step's 7 LDS.64 issue before current
// step's 6 MMAs -> LDS latency hidden behind tensor ops.
// ---------------------------------------------------------------------------

#define Bn    16
#define Cn    64
#define Hn    240
#define Wn    240
#define NP    8
#define NT    512

#define HPn   80
#define WPn   80
#define WBLK  (WPn / NP)          // 10
#define GRID  (Bn * HPn * WBLK)   // 12800

#define SWK2 164          // W pair stride in float2 units (164 mod 16 = 4)
#define SX2  84           // X pair stride in float2 units ( 84 mod 16 = 4)
#define SY   73           // Y stride (floats)

#define W_F   (32 * SWK2 * 2)     // 10496 floats
#define Y_F   (160 * SY)          // 11680 floats
#define WY_F  11680               // max(W_F, Y_F)
#define X_F   (32 * SX2 * 2)      // 5376 floats

// small consts
#define S_B   0                   // biasAll[160]
#define S_WT  160                 // wt[m'][c] 1536
#define S_Q   1696                // q[hd][t]  256
#define S_SZ  1952

#define OFF_X   WY_F              // X2 during GEMM; at/lp (8x320) after
#define OFF_SS  (OFF_X + X_F)
#define SMEM_F  (OFF_SS + S_SZ)       // 19008 floats
#define SMEM_B  (SMEM_F * 4)          // 76032 bytes -> 2 CTAs/SM

__device__ __align__(16) float g_W[W_F];
__device__ __align__(16) float g_small[S_SZ];

__device__ __forceinline__ float to_tf32(float v) {
    unsigned o;
    asm("cvt.rna.tf32.f32 %0, %1;" : "=r"(o) : "f"(v));
    return __uint_as_float(o);
}

__device__ __forceinline__ void mma_tf32(float c[4],
                                         unsigned a0, unsigned a1,
                                         unsigned a2, unsigned a3,
                                         unsigned b0, unsigned b1) {
    asm volatile(
        "mma.sync.aligned.m16n8k8.row.col.f32.tf32.tf32.f32 "
        "{%0,%1,%2,%3}, {%4,%5,%6,%7}, {%8,%9}, {%0,%1,%2,%3};\n"
        : "+f"(c[0]), "+f"(c[1]), "+f"(c[2]), "+f"(c[3])
        : "r"(a0), "r"(a1), "r"(a2), "r"(a3), "r"(b0), "r"(b1));
}

// ---------------- setup: fold constants, build paired W (tf32) -------------
__global__ void setup_kernel(const float* __restrict__ latent,
                             const float* __restrict__ weights,
                             const float* __restrict__ enc_w,
                             const float* __restrict__ enc_b,
                             const float* __restrict__ dec_w,
                             const float* __restrict__ dec_b) {
    int tid = threadIdx.x;
    for (int i = tid; i < 160 * 64; i += 256) {
        int m = i >> 6, k = i & 63;
        float val;
        if (m < 32) {                       // folded scores1: A[c][ht]
            int h = m >> 2, t = m & 3;
            val = 0.f;
            for (int d = 0; d < 8; d++)
                val += latent[h * 32 + t * 8 + d]
                     * enc_w[(h * 16 + 2 * d) * 64 + k];
        } else if (m < 96) {                // v weights
            int hd = m - 32, h = hd >> 3, d = hd & 7;
            val = enc_w[(h * 16 + 2 * d + 1) * 64 + k];
        } else {                            // dec weights
            val = dec_w[(m - 96) * 64 + k];
        }
        // k-interleaved pair layout: kk row holds {W[k], W[k+4]} per m
        int kk = (k >> 3) * 4 + (k & 3);
        int hi = (k >> 2) & 1;
        g_W[(kk * SWK2 + m) * 2 + hi] = to_tf32(val);
    }
    for (int i = tid; i < 160; i += 256) {
        float val;
        if (i < 32) {
            int h = i >> 2, t = i & 3;
            val = 0.f;
            for (int d = 0; d < 8; d++)
                val += latent[h * 32 + t * 8 + d] * enc_b[h * 16 + 2 * d];
        } else if (i < 96) {
            int hd = i - 32, h = hd >> 3, d = hd & 7;
            val = enc_b[h * 16 + 2 * d + 1];
        } else {
            val = dec_b[i - 96];
        }
        g_small[S_B + i] = val;
    }
    for (int i = tid; i < 1536; i += 256) {
        int m = i >> 6, c = i & 63;
        g_small[S_WT + i] = weights[c * 24 + m];
    }
    for (int i = tid; i < 256; i += 256) {
        int hd = i >> 2, t = i & 3;
        int h = hd >> 3, d = hd & 7;
        g_small[S_Q + i] = latent[h * 32 + t * 8 + d];
    }
}

// ---------------- main fused kernel ----------------
__global__ void __launch_bounds__(NT, 2)
nsb_kernel(const float* __restrict__ x, float* __restrict__ out) {
    extern __shared__ float sm[];
    float* wy  = sm;                 // paired W during GEMM, Y afterwards
    float* xs  = sm + OFF_X;         // paired X during GEMM; at/lp after
    float* ss  = sm + OFF_SS;
    float* spb = xs;                 // per-patch at/lp (overlay, 320/patch)

    const int tid = threadIdx.x;

    // W -> smem
    {
        const float4* src = (const float4*)g_W;
        float4* dst = (float4*)wy;
        for (int i = tid; i < W_F / 4; i += NT) dst[i] = src[i];
    }
    for (int i = tid; i < S_SZ; i += NT) ss[i] = g_small[i];

    const int cta  = blockIdx.x;
    const int wblk = cta % WBLK;
    const int hp   = (cta / WBLK) % HPn;
    const int b    = cta / (WBLK * HPn);

    // patchify: float4 loads; X2 pair layout {k, k+4} (raw fp32 -> HW tf32)
    for (int i = tid; i < 1152; i += NT) {
        int c  = i / 18;
        int r  = i - c * 18;
        int p0 = r / 6;
        int q  = r - p0 * 6;
        float4 v = *(const float4*)(x + ((size_t)(b * 64 + c) * Hn
                                         + hp * 3 + p0) * Wn + wblk * 24 + 4 * q);
        int kk = (c >> 3) * 4 + (c & 3);
        int hi = (c >> 2) & 1;
#pragma unroll
        for (int j = 0; j < 4; j++) {
            int col = 4 * q + j;
            int wl = col / 3, p1 = col - wl * 3;
            int n = wl * 9 + p0 * 3 + p1;
            xs[(kk * SX2 + n) * 2 + hi] = ((const float*)&v)[j];
        }
    }
    __syncthreads();

    const int warp = tid >> 5;
    const int lane = tid & 31;
    const int g = lane >> 2, t = lane & 3;

    // ================= GEMM: 15-warp grid 5m x 3n, double-buffered =========
    float acc[2][3][4];
    const int wm = warp / 3, wn = warp - wm * 3;
    const int m0 = wm * 32, n0 = wn * 24;
    if (warp < 15) {
#pragma unroll
        for (int mt = 0; mt < 2; mt++)
#pragma unroll
            for (int nt = 0; nt < 3; nt++)
#pragma unroll
                for (int j = 0; j < 4; j++) acc[mt][nt][j] = 0.f;
        const float2* w2 = (const float2*)wy;
        const float2* x2 = (const float2*)xs;

        float2 bfc[3], aloc[2], ahic[2];      // current frags
        // prologue: load k-step 0 (kk = t)
        {
            int kk = t;
#pragma unroll
            for (int nt = 0; nt < 3; nt++)
                bfc[nt] = x2[kk * SX2 + n0 + nt * 8 + g];
#pragma unroll
            for (int mt = 0; mt < 2; mt++) {
                int mr = m0 + mt * 16;
                aloc[mt] = w2[kk * SWK2 + mr + g];
                ahic[mt] = w2[kk * SWK2 + mr + g + 8];
            }
        }
#pragma unroll
        for (int it = 0; it < 8; it++) {
            float2 bfn[3], alon[2], ahin[2];  // next frags
            if (it < 7) {
                int kk = (it + 1) * 4 + t;
#pragma unroll
                for (int nt = 0; nt < 3; nt++)
                    bfn[nt] = x2[kk * SX2 + n0 + nt * 8 + g];
#pragma unroll
                for (int mt = 0; mt < 2; mt++) {
                    int mr = m0 + mt * 16;
                    alon[mt] = w2[kk * SWK2 + mr + g];
                    ahin[mt] = w2[kk * SWK2 + mr + g + 8];
                }
            }
            // MMAs on current frags (cover next loads' LDS latency)
#pragma unroll
            for (int mt = 0; mt < 2; mt++)
#pragma unroll
                for (int nt = 0; nt < 3; nt++)
                    mma_tf32(acc[mt][nt],
                             __float_as_uint(aloc[mt].x), __float_as_uint(ahic[mt].x),
                             __float_as_uint(aloc[mt].y), __float_as_uint(ahic[mt].y),
                             __float_as_uint(bfc[nt].x),  __float_as_uint(bfc[nt].y));
            if (it < 7) {
#pragma unroll
                for (int nt = 0; nt < 3; nt++) bfc[nt] = bfn[nt];
#pragma unroll
                for (int mt = 0; mt < 2; mt++) {
                    aloc[mt] = alon[mt]; ahic[mt] = ahin[mt];
                }
            }
        }
    }
    __syncthreads();   // all GEMM reads of W/X done -> wy becomes Y, xs free

    if (warp < 15) {
#pragma unroll
        for (int mt = 0; mt < 2; mt++) {
            int r0 = m0 + mt * 16 + g;
            int r1 = r0 + 8;
            float b0 = ss[S_B + r0], b1 = ss[S_B + r1];
#pragma unroll
            for (int nt = 0; nt < 3; nt++) {
                int cc = n0 + nt * 8 + 2 * t;
                wy[r0 * SY + cc]     = acc[mt][nt][0] + b0;
                wy[r0 * SY + cc + 1] = acc[mt][nt][1] + b0;
                wy[r1 * SY + cc]     = acc[mt][nt][2] + b1;
                wy[r1 * SY + cc + 1] = acc[mt][nt][3] + b1;
            }
        }
    }
    __syncthreads();   // Y complete

    // ===== P1: softmax (warps 0-7, warp = patch; lane = ht) =====
    if (warp < 8) {
        float* at = spb + warp * 320;
        float s1[9];
#pragma unroll
        for (int p = 0; p < 9; p++) s1[p] = wy[lane * SY + warp * 9 + p];
        float mx = s1[0];
#pragma unroll
        for (int p = 1; p < 9; p++) mx = fmaxf(mx, s1[p]);
        float sum = 0.f;
#pragma unroll
        for (int p = 0; p < 9; p++) { s1[p] = __expf(s1[p] - mx); sum += s1[p]; }
        float inv = 1.0f / sum;
#pragma unroll
        for (int p = 0; p < 9; p++) at[lane * 9 + p] = s1[p] * inv;
    }
    __syncthreads();

    // ===== P2: lt + spectral, 2 warps/patch (channel halves) =====
    const int patch = warp & 7;
    const int half  = warp >> 3;
    const int ch    = lane + (half << 5);
    float* at = spb + patch * 320;
    float* lp = at;

    float lt[4];
    {
        float v[9];
#pragma unroll
        for (int p = 0; p < 9; p++)
            v[p] = wy[(32 + ch) * SY + patch * 9 + p];
        const int hh = ch >> 3;
#pragma unroll
        for (int tt = 0; tt < 4; tt++) {
            float a = ss[S_Q + ch * 4 + tt];
            const float* r = at + (hh * 4 + tt) * 9;
#pragma unroll
            for (int p = 0; p < 9; p++) a = fmaf(r[p], v[p], a);
            lt[tt] = a;
        }
    }
    __syncthreads();   // all reads of attn1 done before lp overwrite

    // spectral: Chebyshev recurrence, m-outer (2 LDS per m)
    {
        float c2[4], scur[4], ccur[4], sprev[4], cprev[4], acc0[4];
        float w0c = ss[S_WT + 12 * 64 + ch];           // m=0: sin=0, cos=1
#pragma unroll
        for (int tt = 0; tt < 4; tt++) {
            float base = lt[tt] * (float)(CUDART_PI / 12.0);
            float s0, c0;
            __sincosf(base, &s0, &c0);
            c2[tt] = 2.0f * c0;
            scur[tt] = s0; ccur[tt] = c0;
            sprev[tt] = 0.f; cprev[tt] = 1.f;
            acc0[tt] = w0c;
        }
#pragma unroll
        for (int m = 1; m < 12; m++) {
            float ws = ss[S_WT + m * 64 + ch];
            float wc = ss[S_WT + (12 + m) * 64 + ch];
#pragma unroll
            for (int tt = 0; tt < 4; tt++) {
                acc0[tt] = fmaf(scur[tt], ws, fmaf(ccur[tt], wc, acc0[tt]));
                float sn = fmaf(c2[tt], scur[tt], -sprev[tt]);
                float cn = fmaf(c2[tt], ccur[tt], -cprev[tt]);
                sprev[tt] = scur[tt]; cprev[tt] = ccur[tt];
                scur[tt] = sn; ccur[tt] = cn;
            }
        }
#pragma unroll
        for (int tt = 0; tt < 4; tt++)
            lp[ch * 5 + tt] = lt[tt] + acc0[tt];
    }
    __syncthreads();   // lp complete

    // ===== P3: decoder attention, 2 warps/patch (item halves) =====
    {
        float* xq = wy + 96 * SY + patch * 9;
#pragma unroll
        for (int k = 0; k < 2; k++) {
            int item = half * 36 + k * 32 + lane;
            if (k == 0 || lane < 4) {
                int h = item / 9, pos = item - h * 9;
                float sc[4] = {0.f, 0.f, 0.f, 0.f};
#pragma unroll
                for (int d = 0; d < 8; d++) {
                    float xv = xq[(h * 8 + d) * SY + pos];
                    const float* lr = lp + (h * 8 + d) * 5;
#pragma unroll
                    for (int tt = 0; tt < 4; tt++)
                        sc[tt] = fmaf(xv, lr[tt], sc[tt]);
                }
                float m2 = fmaxf(fmaxf(sc[0], sc[1]), fmaxf(sc[2], sc[3]));
                float es = 0.f;
#pragma unroll
                for (int tt = 0; tt < 4; tt++) {
                    sc[tt] = __expf(sc[tt] - m2); es += sc[tt];
                }
                float inv = 1.0f / es;
#pragma unroll
                for (int tt = 0; tt < 4; tt++) sc[tt] *= inv;
#pragma unroll
                for (int d = 0; d < 8; d++) {
                    const float* lr = lp + (h * 8 + d) * 5;
                    float o = 0.f;
#pragma unroll
                    for (int tt = 0; tt < 4; tt++)
                        o = fmaf(sc[tt], lr[tt], o);
                    xq[(h * 8 + d) * SY + pos] = o;
                }
            }
        }
    }
    __syncthreads();

    // un-patchify: float4 residual read + float4 store
    for (int i = tid; i < 1152; i += NT) {
        int c  = i / 18;
        int r  = i - c * 18;
        int p0 = r / 6;
        int q  = r - p0 * 6;
        size_t gbase = ((size_t)(b * 64 + c) * Hn + hp * 3 + p0) * Wn
                       + wblk * 24 + 4 * q;
        float4 rx = *(const float4*)(x + gbase);
        float4 o;
#pragma unroll
        for (int j = 0; j < 4; j++) {
            int col = 4 * q + j;
            int wl = col / 3, p1 = col - wl * 3;
            ((float*)&o)[j] = wy[(96 + c) * SY + wl * 9 + p0 * 3 + p1]
                              + ((const float*)&rx)[j];
        }
        *(float4*)(out + gbase) = o;
    }
}

extern "C" void kernel_launch(void* const* d_in, const int* in_sizes, int n_in,
                              void* d_out, int out_size) {
    const float* x       = (const float*)d_in[0];
    const float* latent  = (const float*)d_in[1];
    const float* weights = (const float*)d_in[2];
    const float* enc_w   = (const float*)d_in[3];
    const float* enc_b   = (const float*)d_in[4];
    const float* dec_w   = (const float*)d_in[5];
    const float* dec_b   = (const float*)d_in[6];
    float* out = (float*)d_out;

    cudaFuncSetAttribute(nsb_kernel,
                         cudaFuncAttributeMaxDynamicSharedMemorySize, SMEM_B);

    setup_kernel<<<1, 256>>>(latent, weights, enc_w, enc_b, dec_w, dec_b);
    nsb_kernel<<<GRID, NT, SMEM_B>>>(x, out);
}